// round 16
// baseline (speedup 1.0000x reference)
#include <cuda_runtime.h>

// Problem constants (fixed by the reference: S=256, B=256, D=1024, MAX_LEN=256)
#define S_DIM 256
#define B_DIM 256
#define D_DIM 1024
#define DV    (D_DIM / 4)   // 256 float4 per row
#define BPB   64            // batch elements per block

// Single fused kernel.
//   grid = (S_DIM, B_DIM / BPB) = (256, 4), block = 256 threads.
//   Each block owns one s and 64 consecutive b.
//   Per-thread (one float4 of d): de-interleave W_xy, fold pe+b_xy+b_seg,
//   all from L2-resident broadcast loads, amortized over 64 iterations.
//   x tile for the block is staged into shared memory as PADDED float4
//   ({x0,x1,x2,0}) so the hot loop is exactly:
//       1 broadcast LDS.128 + 12 FMA + 1 STG.128 (streaming)
//   -> 5 L1 wavefronts per 4 wavefronts of store data (was 7/4 in R14).
__global__ __launch_bounds__(256) void pe_fused_kernel(
    const float* __restrict__ x,      // [S,B,3]
    const float* __restrict__ W_xy,   // [D,2] interleaved
    const float* __restrict__ b_xy,   // [D]
    const float* __restrict__ W_seg,  // [D,1]
    const float* __restrict__ b_seg,  // [D]
    const float* __restrict__ pe,     // [MAX_LEN,1,D]
    float* __restrict__ out)          // [S,B,D]
{
    __shared__ float4 s_x4[BPB];      // 1 KB, padded x rows

    const int s  = blockIdx.x;
    const int b0 = blockIdx.y * BPB;
    const int tv = threadIdx.x;       // float4 index along d
    const int d  = tv * 4;

    // Stage this block's x slice, repacked to float4 with padding.
    // Threads 0..63: 3 scalar LDG (contiguous across the warp) + 1 STS.128.
    if (tv < BPB) {
        const float* xp = x + ((size_t)s * B_DIM + b0 + tv) * 3;
        s_x4[tv] = make_float4(xp[0], xp[1], xp[2], 0.0f);
    }

    // Per-thread setup (L2-hit broadcast loads, once per 64 stores).
    // W_xy rows d..d+3, 2 floats each = 8 contiguous floats (32B-aligned).
    const float4 a  = *reinterpret_cast<const float4*>(W_xy + 2 * d);
    const float4 bq = *reinterpret_cast<const float4*>(W_xy + 2 * d + 4);
    const float4 w0 = make_float4(a.x, a.z, bq.x, bq.z);   // column 0
    const float4 w1 = make_float4(a.y, a.w, bq.y, bq.w);   // column 1
    const float4 ws = *reinterpret_cast<const float4*>(W_seg + d);

    const float4 p  = *reinterpret_cast<const float4*>(pe    + (size_t)s * D_DIM + d);
    const float4 bx = *reinterpret_cast<const float4*>(b_xy  + d);
    const float4 bs = *reinterpret_cast<const float4*>(b_seg + d);
    const float4 pc = make_float4(p.x + bx.x + bs.x,
                                  p.y + bx.y + bs.y,
                                  p.z + bx.z + bs.z,
                                  p.w + bx.w + bs.w);

    __syncthreads();

    float4* op = reinterpret_cast<float4*>(out)
               + ((size_t)s * B_DIM + b0) * DV + tv;

#pragma unroll 4
    for (int i = 0; i < BPB; ++i) {
        const float4 xv = s_x4[i];    // single broadcast LDS.128

        float4 r;
        r.x = fmaf(xv.x, w0.x, fmaf(xv.y, w1.x, fmaf(xv.z, ws.x, pc.x)));
        r.y = fmaf(xv.x, w0.y, fmaf(xv.y, w1.y, fmaf(xv.z, ws.y, pc.y)));
        r.z = fmaf(xv.x, w0.z, fmaf(xv.y, w1.z, fmaf(xv.z, ws.z, pc.z)));
        r.w = fmaf(xv.x, w0.w, fmaf(xv.y, w1.w, fmaf(xv.z, ws.w, pc.w)));

        // Streaming store: output is never re-read, don't pollute L2.
        __stcs(op, r);
        op += DV;
    }
}

// ---------------------------------------------------------------------------
// Harness entry. Input order per metadata: x, W_xy, b_xy, W_seg, b_seg, pe.
// ---------------------------------------------------------------------------
extern "C" void kernel_launch(void* const* d_in, const int* in_sizes, int n_in,
                              void* d_out, int out_size)
{
    const float* x     = (const float*)d_in[0];
    const float* W_xy  = (const float*)d_in[1];
    const float* b_xy  = (const float*)d_in[2];
    const float* W_seg = (const float*)d_in[3];
    const float* b_seg = (const float*)d_in[4];
    const float* pe    = (const float*)d_in[5];
    float* out = (float*)d_out;

    dim3 grid(S_DIM, B_DIM / BPB);
    pe_fused_kernel<<<grid, 256>>>(x, W_xy, b_xy, W_seg, b_seg, pe, out);
}